// round 1
// baseline (speedup 1.0000x reference)
#include <cuda_runtime.h>
#include <math.h>

// Problem constants
#define Bv   32
#define Sv   512
#define Dv   768
#define Mv   32
#define Tv   30
#define Hv   12
#define HDv  64
#define DFFv 3072
#define Lv   4
#define Ev   100000
#define NT   1024           // B*M token rows

// ---------------- scratch (static device memory; no allocations) -------------
__device__ float g_x[NT * Dv];        // residual stream [1024,768]
__device__ float g_qkv[NT * 3 * Dv];  // [1024,2304]
__device__ float g_buf1[NT * DFFv];   // attn-out [1024,768] / FF hidden [1024,3072]
__device__ float g_buf2[NT * Dv];     // proj results
__device__ float g_hid[NT * 100];     // classifier hidden

// ======================= mention pooling ====================================
// x[b,m,:] = sum_t softmax_t(logit)_t * (valid[t] ? lhs[b,t,:] : 0)
// logit[t] = (valid[t] ? dot(lhs[b,t,:], attn_w) : 0) + attn_b
// valid[t] = emask[b,m] && all(pos[b,m,0..t] != -1)
__global__ void __launch_bounds__(128) pool_kernel(
    const float* __restrict__ lhs, const float* __restrict__ attn_w,
    const float* __restrict__ attn_b_p, const int* __restrict__ pos,
    const int* __restrict__ emask, float* __restrict__ x)
{
    int bm = blockIdx.x;
    int b = bm / Mv;
    __shared__ float logit[Tv];
    __shared__ float score[Tv];
    __shared__ int   validv[Tv];

    int tid = threadIdx.x, lane = tid & 31, warp = tid >> 5;

    if (tid == 0) {
        int ok = (emask[bm] != 0);
        int alive = 1;
        for (int t = 0; t < Tv; t++) {
            if (pos[bm * Tv + t] == -1) alive = 0;
            validv[t] = ok & alive;
        }
    }
    __syncthreads();

    float ab = attn_b_p[0];
    const float* lb = lhs + (size_t)b * Sv * Dv;

    // logits: one warp per token slot (round-robin)
    for (int t = warp; t < Tv; t += 4) {
        float s = 0.f;
        for (int d = lane; d < Dv; d += 32) s += lb[t * Dv + d] * attn_w[d];
        for (int o = 16; o; o >>= 1) s += __shfl_xor_sync(0xffffffffu, s, o);
        if (lane == 0) logit[t] = (validv[t] ? s : 0.f) + ab;
    }
    __syncthreads();

    // softmax over T in warp 0
    if (tid < 32) {
        float v = (tid < Tv) ? logit[tid] : -INFINITY;
        float mx = v;
        for (int o = 16; o; o >>= 1) mx = fmaxf(mx, __shfl_xor_sync(0xffffffffu, mx, o));
        float e = (tid < Tv) ? expf(v - mx) : 0.f;
        float sm = e;
        for (int o = 16; o; o >>= 1) sm += __shfl_xor_sync(0xffffffffu, sm, o);
        if (tid < Tv) score[tid] = e / sm;
    }
    __syncthreads();

    for (int d = tid; d < Dv; d += 128) {
        float s = 0.f;
        #pragma unroll
        for (int t = 0; t < Tv; t++)
            if (validv[t]) s += score[t] * lb[t * Dv + d];
        x[(size_t)bm * Dv + d] = s;
    }
}

// ======================= generic GEMM: C = A @ W^T (+bias, +relu) ===========
// A: [Mr,K] row-major, W: [N,K] row-major, C: [Mr,N]. Mr multiple of 64.
#define BM_ 64
#define BN_ 64
#define BK_ 16

__global__ void __launch_bounds__(256) gemm_kernel(
    const float* __restrict__ A, const float* __restrict__ W,
    const float* __restrict__ bias, float* __restrict__ C,
    int N, int K, int relu)
{
    __shared__ float As[BK_][BM_];
    __shared__ float Ws[BK_][BN_];

    const int tid = threadIdx.x;
    const int tx = tid & 15, ty = tid >> 4;
    const int rowBase = blockIdx.y * BM_;
    const int colBase = blockIdx.x * BN_;
    const int lr = tid >> 2;          // 0..63
    const int lk = (tid & 3) << 2;    // 0,4,8,12

    const float* Ap = A + (size_t)(rowBase + lr) * K;
    const bool  wok = (colBase + lr) < N;
    const float* Wp = wok ? (W + (size_t)(colBase + lr) * K) : W;

    float acc[4][4] = {{0.f}};

    for (int k0 = 0; k0 < K; k0 += BK_) {
        float4 av, wv;
        if (k0 + BK_ <= K) {
            av = *(const float4*)(Ap + k0 + lk);
            if (wok) wv = *(const float4*)(Wp + k0 + lk);
            else     wv = make_float4(0.f, 0.f, 0.f, 0.f);
        } else {
            float ta[4], tw[4];
            #pragma unroll
            for (int i = 0; i < 4; i++) {
                int kk = k0 + lk + i;
                ta[i] = (kk < K) ? Ap[kk] : 0.f;
                tw[i] = (wok && kk < K) ? Wp[kk] : 0.f;
            }
            av = make_float4(ta[0], ta[1], ta[2], ta[3]);
            wv = make_float4(tw[0], tw[1], tw[2], tw[3]);
        }
        As[lk + 0][lr] = av.x; As[lk + 1][lr] = av.y;
        As[lk + 2][lr] = av.z; As[lk + 3][lr] = av.w;
        Ws[lk + 0][lr] = wv.x; Ws[lk + 1][lr] = wv.y;
        Ws[lk + 2][lr] = wv.z; Ws[lk + 3][lr] = wv.w;
        __syncthreads();

        #pragma unroll
        for (int k = 0; k < BK_; k++) {
            float4 a4 = *(const float4*)&As[k][ty << 2];
            float4 b4 = *(const float4*)&Ws[k][tx << 2];
            acc[0][0] += a4.x * b4.x; acc[0][1] += a4.x * b4.y;
            acc[0][2] += a4.x * b4.z; acc[0][3] += a4.x * b4.w;
            acc[1][0] += a4.y * b4.x; acc[1][1] += a4.y * b4.y;
            acc[1][2] += a4.y * b4.z; acc[1][3] += a4.y * b4.w;
            acc[2][0] += a4.z * b4.x; acc[2][1] += a4.z * b4.y;
            acc[2][2] += a4.z * b4.z; acc[2][3] += a4.z * b4.w;
            acc[3][0] += a4.w * b4.x; acc[3][1] += a4.w * b4.y;
            acc[3][2] += a4.w * b4.z; acc[3][3] += a4.w * b4.w;
        }
        __syncthreads();
    }

    #pragma unroll
    for (int i = 0; i < 4; i++) {
        int row = rowBase + (ty << 2) + i;
        int col0 = colBase + (tx << 2);
        if (col0 + 3 < N) {
            float4 v;
            v.x = acc[i][0]; v.y = acc[i][1]; v.z = acc[i][2]; v.w = acc[i][3];
            if (bias) {
                v.x += bias[col0 + 0]; v.y += bias[col0 + 1];
                v.z += bias[col0 + 2]; v.w += bias[col0 + 3];
            }
            if (relu) {
                v.x = fmaxf(v.x, 0.f); v.y = fmaxf(v.y, 0.f);
                v.z = fmaxf(v.z, 0.f); v.w = fmaxf(v.w, 0.f);
            }
            *(float4*)&C[(size_t)row * N + col0] = v;
        } else {
            #pragma unroll
            for (int j = 0; j < 4; j++) {
                int col = col0 + j;
                if (col < N) {
                    float v = acc[i][j] + (bias ? bias[col] : 0.f);
                    if (relu) v = fmaxf(v, 0.f);
                    C[(size_t)row * N + col] = v;
                }
            }
        }
    }
}

// ======================= attention (seq 32, hd 64), one block per (b,h) =====
__global__ void __launch_bounds__(256) attn_kernel(
    const float* __restrict__ qkv, float* __restrict__ o)
{
    const int bh = blockIdx.x;
    const int b = bh / Hv, h = bh % Hv;
    __shared__ float q[32][68];
    __shared__ float kk[32][68];
    __shared__ float vv[32][68];
    __shared__ float a[32][33];

    const int tid = threadIdx.x;
    const float* base = qkv + (size_t)(b * Mv) * (3 * Dv) + h * HDv;

    for (int idx = tid; idx < 32 * 64; idx += 256) {
        int i = idx >> 6, d = idx & 63;
        const float* row = base + (size_t)i * (3 * Dv) + d;
        q[i][d]  = row[0];
        kk[i][d] = row[Dv];
        vv[i][d] = row[2 * Dv];
    }
    __syncthreads();

    // scores: s[i][j] = (q_i . k_j) / 8
    for (int idx = tid; idx < 1024; idx += 256) {
        int i = idx >> 5, j = idx & 31;
        float s = 0.f;
        #pragma unroll
        for (int d = 0; d < 64; d += 4) {
            float4 qa = *(const float4*)&q[i][d];
            float4 ka = *(const float4*)&kk[j][d];
            s += qa.x * ka.x + qa.y * ka.y + qa.z * ka.z + qa.w * ka.w;
        }
        a[i][j] = s * 0.125f;
    }
    __syncthreads();

    // row softmax: warp per row (8 warps x 4 rows)
    int warp = tid >> 5, lane = tid & 31;
    for (int i = warp; i < 32; i += 8) {
        float v = a[i][lane];
        float mx = v;
        for (int off = 16; off; off >>= 1) mx = fmaxf(mx, __shfl_xor_sync(0xffffffffu, mx, off));
        float e = expf(v - mx);
        float sm = e;
        for (int off = 16; off; off >>= 1) sm += __shfl_xor_sync(0xffffffffu, sm, off);
        a[i][lane] = e / sm;
    }
    __syncthreads();

    // o = a @ v
    float* obase = o + (size_t)(b * Mv) * Dv + h * HDv;
    for (int idx = tid; idx < 2048; idx += 256) {
        int i = idx >> 6, d = idx & 63;
        float s = 0.f;
        #pragma unroll
        for (int j = 0; j < 32; j++) s += a[i][j] * vv[j][d];
        obase[(size_t)i * Dv + d] = s;
    }
}

// ======================= residual add + LayerNorm (post-LN) =================
__global__ void __launch_bounds__(256) addln_kernel(
    float* __restrict__ x, const float* __restrict__ d,
    const float* __restrict__ w, const float* __restrict__ b)
{
    __shared__ float sh[8];
    __shared__ float s_mean, s_inv;
    const int row = blockIdx.x;
    float* xr = x + (size_t)row * Dv;
    const float* dr = d + (size_t)row * Dv;
    const int tid = threadIdx.x, lane = tid & 31, warp = tid >> 5;

    float v[3];
    float sum = 0.f;
    #pragma unroll
    for (int i = 0; i < 3; i++) {
        int idx = tid + 256 * i;
        v[i] = xr[idx] + dr[idx];
        sum += v[i];
    }
    for (int o = 16; o; o >>= 1) sum += __shfl_xor_sync(0xffffffffu, sum, o);
    if (lane == 0) sh[warp] = sum;
    __syncthreads();
    if (tid == 0) {
        float s = 0.f;
        for (int i = 0; i < 8; i++) s += sh[i];
        s_mean = s * (1.f / (float)Dv);
    }
    __syncthreads();
    float mean = s_mean;

    float sq = 0.f;
    #pragma unroll
    for (int i = 0; i < 3; i++) { float c = v[i] - mean; sq += c * c; }
    for (int o = 16; o; o >>= 1) sq += __shfl_xor_sync(0xffffffffu, sq, o);
    if (lane == 0) sh[warp] = sq;
    __syncthreads();
    if (tid == 0) {
        float s = 0.f;
        for (int i = 0; i < 8; i++) s += sh[i];
        s_inv = rsqrtf(s * (1.f / (float)Dv) + 1e-5f);
    }
    __syncthreads();
    float inv = s_inv;

    #pragma unroll
    for (int i = 0; i < 3; i++) {
        int idx = tid + 256 * i;
        xr[idx] = (v[i] - mean) * inv * w[idx] + b[idx];
    }
}

// ======================= launcher ===========================================
extern "C" void kernel_launch(void* const* d_in, const int* in_sizes, int n_in,
                              void* d_out, int out_size)
{
    const float* lhs       = (const float*)d_in[0];
    const float* attn_w    = (const float*)d_in[1];
    const float* attn_b    = (const float*)d_in[2];
    const float* in_proj_w = (const float*)d_in[3];
    const float* in_proj_b = (const float*)d_in[4];
    const float* out_w     = (const float*)d_in[5];
    const float* out_b     = (const float*)d_in[6];
    const float* ln1_w     = (const float*)d_in[7];
    const float* ln1_b     = (const float*)d_in[8];
    const float* lin1_w    = (const float*)d_in[9];
    const float* lin1_b    = (const float*)d_in[10];
    const float* lin2_w    = (const float*)d_in[11];
    const float* lin2_b    = (const float*)d_in[12];
    const float* ln2_w     = (const float*)d_in[13];
    const float* ln2_b     = (const float*)d_in[14];
    const float* cls_w1    = (const float*)d_in[15];
    const float* cls_w2    = (const float*)d_in[16];
    const float* cls_b2    = (const float*)d_in[17];
    const int*   pos       = (const int*)d_in[18];
    const int*   emask     = (const int*)d_in[19];
    float* out = (float*)d_out;

    float *x, *qkv, *buf1, *buf2, *hid;
    cudaGetSymbolAddress((void**)&x,    g_x);
    cudaGetSymbolAddress((void**)&qkv,  g_qkv);
    cudaGetSymbolAddress((void**)&buf1, g_buf1);
    cudaGetSymbolAddress((void**)&buf2, g_buf2);
    cudaGetSymbolAddress((void**)&hid,  g_hid);

    pool_kernel<<<NT, 128>>>(lhs, attn_w, attn_b, pos, emask, x);

    for (int l = 0; l < Lv; l++) {
        // QKV projection
        gemm_kernel<<<dim3(36, 16), 256>>>(
            x, in_proj_w + (size_t)l * 3 * Dv * Dv, in_proj_b + (size_t)l * 3 * Dv,
            qkv, 3 * Dv, Dv, 0);
        // self-attention
        attn_kernel<<<Bv * Hv, 256>>>(qkv, buf1);
        // output projection
        gemm_kernel<<<dim3(12, 16), 256>>>(
            buf1, out_w + (size_t)l * Dv * Dv, out_b + (size_t)l * Dv,
            buf2, Dv, Dv, 0);
        addln_kernel<<<NT, 256>>>(x, buf2, ln1_w + (size_t)l * Dv, ln1_b + (size_t)l * Dv);
        // FFN
        gemm_kernel<<<dim3(48, 16), 256>>>(
            x, lin1_w + (size_t)l * DFFv * Dv, lin1_b + (size_t)l * DFFv,
            buf1, DFFv, Dv, 1);
        gemm_kernel<<<dim3(12, 16), 256>>>(
            buf1, lin2_w + (size_t)l * Dv * DFFv, lin2_b + (size_t)l * Dv,
            buf2, Dv, DFFv, 0);
        addln_kernel<<<NT, 256>>>(x, buf2, ln2_w + (size_t)l * Dv, ln2_b + (size_t)l * Dv);
    }

    // classifier
    gemm_kernel<<<dim3(2, 16), 256>>>(x, cls_w1, nullptr, hid, 100, Dv, 0);
    gemm_kernel<<<dim3(1563, 16), 256>>>(hid, cls_w2, cls_b2, out, Ev, 100, 0);
}

// round 2
// speedup vs baseline: 1.9937x; 1.9937x over previous
#include <cuda_runtime.h>
#include <math.h>
#include <stdint.h>

// Problem constants
#define Bv   32
#define Sv   512
#define Dv   768
#define Mv   32
#define Tv   30
#define Hv   12
#define HDv  64
#define DFFv 3072
#define Lv   4
#define Ev   100000
#define NT   1024           // B*M token rows

// ---------------- scratch (static device memory; no allocations) -------------
__device__ float g_x[NT * Dv];        // residual stream [1024,768]
__device__ float g_qkv[NT * 3 * Dv];  // [1024,2304]
__device__ float g_buf1[NT * DFFv];   // attn-out / FF hidden
__device__ float g_buf2[NT * Dv];     // proj results
__device__ float g_hid[NT * 100];     // classifier hidden

// ======================= helpers ============================================
__device__ __forceinline__ uint32_t f2tf32(float f) {
    uint32_t u;
    asm("cvt.rna.tf32.f32 %0, %1;" : "=r"(u) : "f"(f));
    return u;
}

__device__ __forceinline__ void mma_tf32(float* c, const uint32_t* a, const uint32_t* b) {
    asm volatile(
        "mma.sync.aligned.m16n8k8.row.col.f32.tf32.tf32.f32 "
        "{%0,%1,%2,%3}, {%4,%5,%6,%7}, {%8,%9}, {%0,%1,%2,%3};"
        : "+f"(c[0]), "+f"(c[1]), "+f"(c[2]), "+f"(c[3])
        : "r"(a[0]), "r"(a[1]), "r"(a[2]), "r"(a[3]),
          "r"(b[0]), "r"(b[1]));
}

// ======================= mention pooling ====================================
__global__ void __launch_bounds__(128) pool_kernel(
    const float* __restrict__ lhs, const float* __restrict__ attn_w,
    const float* __restrict__ attn_b_p, const int* __restrict__ pos,
    const int* __restrict__ emask, float* __restrict__ x)
{
    int bm = blockIdx.x;
    int b = bm / Mv;
    __shared__ float logit[Tv];
    __shared__ float score[Tv];
    __shared__ int   validv[Tv];

    int tid = threadIdx.x, lane = tid & 31, warp = tid >> 5;

    if (tid == 0) {
        int ok = (emask[bm] != 0);
        int alive = 1;
        for (int t = 0; t < Tv; t++) {
            if (pos[bm * Tv + t] == -1) alive = 0;
            validv[t] = ok & alive;
        }
    }
    __syncthreads();

    float ab = attn_b_p[0];
    const float* lb = lhs + (size_t)b * Sv * Dv;

    for (int t = warp; t < Tv; t += 4) {
        float s = 0.f;
        for (int d = lane; d < Dv; d += 32) s += lb[t * Dv + d] * attn_w[d];
        for (int o = 16; o; o >>= 1) s += __shfl_xor_sync(0xffffffffu, s, o);
        if (lane == 0) logit[t] = (validv[t] ? s : 0.f) + ab;
    }
    __syncthreads();

    if (tid < 32) {
        float v = (tid < Tv) ? logit[tid] : -INFINITY;
        float mx = v;
        for (int o = 16; o; o >>= 1) mx = fmaxf(mx, __shfl_xor_sync(0xffffffffu, mx, o));
        float e = (tid < Tv) ? expf(v - mx) : 0.f;
        float sm = e;
        for (int o = 16; o; o >>= 1) sm += __shfl_xor_sync(0xffffffffu, sm, o);
        if (tid < Tv) score[tid] = e / sm;
    }
    __syncthreads();

    for (int d = tid; d < Dv; d += 128) {
        float s = 0.f;
        #pragma unroll
        for (int t = 0; t < Tv; t++)
            if (validv[t]) s += score[t] * lb[t * Dv + d];
        x[(size_t)bm * Dv + d] = s;
    }
}

// ======================= TF32 tensor-core GEMM ==============================
// C = A @ W^T (+bias, +relu). A:[M,K] fp32 row-major, W:[N,K] fp32 row-major.
// M multiple of 64. Tile 64x64x32, 4 warps (2x2 of 32x32), double-buffered.
#define BK_ 32

__device__ __forceinline__ void gmem_load_tiles(
    const float* __restrict__ A, const float* __restrict__ W,
    int rowBase, int colBase, int N, int K, int k0, int row, int kq,
    float4* ra, float4* rw)
{
    const bool fast = (k0 + BK_ <= K);
    const float* Ap = A + (size_t)(rowBase + row) * K + k0 + kq;
    if (fast) {
        #pragma unroll
        for (int q = 0; q < 4; q++) ra[q] = *(const float4*)(Ap + q * 4);
    } else {
        #pragma unroll
        for (int q = 0; q < 4; q++) {
            float t[4];
            #pragma unroll
            for (int j = 0; j < 4; j++) {
                int kk = k0 + kq + q * 4 + j;
                t[j] = (kk < K) ? Ap[q * 4 + j] : 0.f;
            }
            ra[q] = make_float4(t[0], t[1], t[2], t[3]);
        }
    }
    int wrow = colBase + row;
    if (wrow < N) {
        const float* Wp = W + (size_t)wrow * K + k0 + kq;
        if (fast) {
            #pragma unroll
            for (int q = 0; q < 4; q++) rw[q] = *(const float4*)(Wp + q * 4);
        } else {
            #pragma unroll
            for (int q = 0; q < 4; q++) {
                float t[4];
                #pragma unroll
                for (int j = 0; j < 4; j++) {
                    int kk = k0 + kq + q * 4 + j;
                    t[j] = (kk < K) ? Wp[q * 4 + j] : 0.f;
                }
                rw[q] = make_float4(t[0], t[1], t[2], t[3]);
            }
        }
    } else {
        #pragma unroll
        for (int q = 0; q < 4; q++) rw[q] = make_float4(0.f, 0.f, 0.f, 0.f);
    }
}

__device__ __forceinline__ void smem_store_tiles(
    uint32_t (*As)[72], uint32_t (*Ws)[36],
    int row, int kq, const float4* ra, const float4* rw)
{
    #pragma unroll
    for (int q = 0; q < 4; q++) {
        // A: transposed [k][m]
        As[kq + q * 4 + 0][row] = f2tf32(ra[q].x);
        As[kq + q * 4 + 1][row] = f2tf32(ra[q].y);
        As[kq + q * 4 + 2][row] = f2tf32(ra[q].z);
        As[kq + q * 4 + 3][row] = f2tf32(ra[q].w);
        // W: [n][k], vector store (row stride 36*4=144B, 16B-aligned)
        uint4 wv;
        wv.x = f2tf32(rw[q].x); wv.y = f2tf32(rw[q].y);
        wv.z = f2tf32(rw[q].z); wv.w = f2tf32(rw[q].w);
        *(uint4*)&Ws[row][kq + q * 4] = wv;
    }
}

__global__ void __launch_bounds__(128) gemm_tf32_kernel(
    const float* __restrict__ A, const float* __restrict__ W,
    const float* __restrict__ bias, float* __restrict__ C,
    int N, int K, int relu)
{
    __shared__ __align__(16) uint32_t As[2][BK_][72];  // [k][m]
    __shared__ __align__(16) uint32_t Ws[2][64][36];   // [n][k]

    const int tid = threadIdx.x;
    const int lane = tid & 31, wid = tid >> 5;
    const int wy = wid >> 1, wx = wid & 1;
    const int lm = lane >> 2, lk = lane & 3;
    const int rowBase = blockIdx.y * 64;
    const int colBase = blockIdx.x * 64;
    const int row = tid >> 1;            // 0..63
    const int kq  = (tid & 1) * 16;      // 0 or 16

    float acc[2][4][4];
    #pragma unroll
    for (int i = 0; i < 2; i++)
        #pragma unroll
        for (int j = 0; j < 4; j++)
            #pragma unroll
            for (int q = 0; q < 4; q++) acc[i][j][q] = 0.f;

    const int nT = (K + BK_ - 1) / BK_;
    float4 ra[4], rw[4];

    // preload tile 0
    gmem_load_tiles(A, W, rowBase, colBase, N, K, 0, row, kq, ra, rw);
    smem_store_tiles(As[0], Ws[0], row, kq, ra, rw);
    __syncthreads();

    for (int t = 0; t < nT; t++) {
        const int cur = t & 1;
        const bool more = (t + 1) < nT;
        if (more)
            gmem_load_tiles(A, W, rowBase, colBase, N, K, (t + 1) * BK_, row, kq, ra, rw);

        #pragma unroll
        for (int k8 = 0; k8 < 4; k8++) {
            const int kb = k8 * 8;
            uint32_t a[2][4], b[4][2];
            #pragma unroll
            for (int mt = 0; mt < 2; mt++) {
                int m = wy * 32 + mt * 16 + lm;
                a[mt][0] = As[cur][kb + lk][m];
                a[mt][1] = As[cur][kb + lk][m + 8];
                a[mt][2] = As[cur][kb + 4 + lk][m];
                a[mt][3] = As[cur][kb + 4 + lk][m + 8];
            }
            #pragma unroll
            for (int nt = 0; nt < 4; nt++) {
                int n = wx * 32 + nt * 8 + lm;
                b[nt][0] = Ws[cur][n][kb + lk];
                b[nt][1] = Ws[cur][n][kb + 4 + lk];
            }
            #pragma unroll
            for (int mt = 0; mt < 2; mt++)
                #pragma unroll
                for (int nt = 0; nt < 4; nt++)
                    mma_tf32(acc[mt][nt], a[mt], b[nt]);
        }

        if (more)
            smem_store_tiles(As[cur ^ 1], Ws[cur ^ 1], row, kq, ra, rw);
        __syncthreads();
    }

    // epilogue
    #pragma unroll
    for (int mt = 0; mt < 2; mt++) {
        #pragma unroll
        for (int nt = 0; nt < 4; nt++) {
            int r0 = rowBase + wy * 32 + mt * 16 + lm;
            int c0 = colBase + wx * 32 + nt * 8 + lk * 2;
            float bx = 0.f, by = 0.f;
            if (bias) {
                if (c0 < N)     bx = bias[c0];
                if (c0 + 1 < N) by = bias[c0 + 1];
            }
            float v00 = acc[mt][nt][0] + bx, v01 = acc[mt][nt][1] + by;
            float v10 = acc[mt][nt][2] + bx, v11 = acc[mt][nt][3] + by;
            if (relu) {
                v00 = fmaxf(v00, 0.f); v01 = fmaxf(v01, 0.f);
                v10 = fmaxf(v10, 0.f); v11 = fmaxf(v11, 0.f);
            }
            if (c0 + 1 < N) {
                float2 p0 = make_float2(v00, v01);
                float2 p1 = make_float2(v10, v11);
                *(float2*)&C[(size_t)r0 * N + c0]       = p0;
                *(float2*)&C[(size_t)(r0 + 8) * N + c0] = p1;
            } else if (c0 < N) {
                C[(size_t)r0 * N + c0]       = v00;
                C[(size_t)(r0 + 8) * N + c0] = v10;
            }
        }
    }
}

// ======================= attention (seq 32, hd 64), one block per (b,h) =====
__global__ void __launch_bounds__(256) attn_kernel(
    const float* __restrict__ qkv, float* __restrict__ o)
{
    const int bh = blockIdx.x;
    const int b = bh / Hv, h = bh % Hv;
    __shared__ float q[32][68];
    __shared__ float kk[32][68];
    __shared__ float vv[32][68];
    __shared__ float a[32][33];

    const int tid = threadIdx.x;
    const float* base = qkv + (size_t)(b * Mv) * (3 * Dv) + h * HDv;

    for (int idx = tid; idx < 32 * 64; idx += 256) {
        int i = idx >> 6, d = idx & 63;
        const float* row = base + (size_t)i * (3 * Dv) + d;
        q[i][d]  = row[0];
        kk[i][d] = row[Dv];
        vv[i][d] = row[2 * Dv];
    }
    __syncthreads();

    for (int idx = tid; idx < 1024; idx += 256) {
        int i = idx >> 5, j = idx & 31;
        float s = 0.f;
        #pragma unroll
        for (int d = 0; d < 64; d += 4) {
            float4 qa = *(const float4*)&q[i][d];
            float4 ka = *(const float4*)&kk[j][d];
            s += qa.x * ka.x + qa.y * ka.y + qa.z * ka.z + qa.w * ka.w;
        }
        a[i][j] = s * 0.125f;
    }
    __syncthreads();

    int warp = tid >> 5, lane = tid & 31;
    for (int i = warp; i < 32; i += 8) {
        float v = a[i][lane];
        float mx = v;
        for (int off = 16; off; off >>= 1) mx = fmaxf(mx, __shfl_xor_sync(0xffffffffu, mx, off));
        float e = expf(v - mx);
        float sm = e;
        for (int off = 16; off; off >>= 1) sm += __shfl_xor_sync(0xffffffffu, sm, off);
        a[i][lane] = e / sm;
    }
    __syncthreads();

    float* obase = o + (size_t)(b * Mv) * Dv + h * HDv;
    for (int idx = tid; idx < 2048; idx += 256) {
        int i = idx >> 6, d = idx & 63;
        float s = 0.f;
        #pragma unroll
        for (int j = 0; j < 32; j++) s += a[i][j] * vv[j][d];
        obase[(size_t)i * Dv + d] = s;
    }
}

// ======================= residual add + LayerNorm (post-LN) =================
__global__ void __launch_bounds__(256) addln_kernel(
    float* __restrict__ x, const float* __restrict__ d,
    const float* __restrict__ w, const float* __restrict__ b)
{
    __shared__ float sh[8];
    __shared__ float s_mean, s_inv;
    const int row = blockIdx.x;
    float* xr = x + (size_t)row * Dv;
    const float* dr = d + (size_t)row * Dv;
    const int tid = threadIdx.x, lane = tid & 31, warp = tid >> 5;

    float v[3];
    float sum = 0.f;
    #pragma unroll
    for (int i = 0; i < 3; i++) {
        int idx = tid + 256 * i;
        v[i] = xr[idx] + dr[idx];
        sum += v[i];
    }
    for (int o = 16; o; o >>= 1) sum += __shfl_xor_sync(0xffffffffu, sum, o);
    if (lane == 0) sh[warp] = sum;
    __syncthreads();
    if (tid == 0) {
        float s = 0.f;
        for (int i = 0; i < 8; i++) s += sh[i];
        s_mean = s * (1.f / (float)Dv);
    }
    __syncthreads();
    float mean = s_mean;

    float sq = 0.f;
    #pragma unroll
    for (int i = 0; i < 3; i++) { float c = v[i] - mean; sq += c * c; }
    for (int o = 16; o; o >>= 1) sq += __shfl_xor_sync(0xffffffffu, sq, o);
    if (lane == 0) sh[warp] = sq;
    __syncthreads();
    if (tid == 0) {
        float s = 0.f;
        for (int i = 0; i < 8; i++) s += sh[i];
        s_inv = rsqrtf(s * (1.f / (float)Dv) + 1e-5f);
    }
    __syncthreads();
    float inv = s_inv;

    #pragma unroll
    for (int i = 0; i < 3; i++) {
        int idx = tid + 256 * i;
        xr[idx] = (v[i] - mean) * inv * w[idx] + b[idx];
    }
}

// ======================= launcher ===========================================
extern "C" void kernel_launch(void* const* d_in, const int* in_sizes, int n_in,
                              void* d_out, int out_size)
{
    const float* lhs       = (const float*)d_in[0];
    const float* attn_w    = (const float*)d_in[1];
    const float* attn_b    = (const float*)d_in[2];
    const float* in_proj_w = (const float*)d_in[3];
    const float* in_proj_b = (const float*)d_in[4];
    const float* out_w     = (const float*)d_in[5];
    const float* out_b     = (const float*)d_in[6];
    const float* ln1_w     = (const float*)d_in[7];
    const float* ln1_b     = (const float*)d_in[8];
    const float* lin1_w    = (const float*)d_in[9];
    const float* lin1_b    = (const float*)d_in[10];
    const float* lin2_w    = (const float*)d_in[11];
    const float* lin2_b    = (const float*)d_in[12];
    const float* ln2_w     = (const float*)d_in[13];
    const float* ln2_b     = (const float*)d_in[14];
    const float* cls_w1    = (const float*)d_in[15];
    const float* cls_w2    = (const float*)d_in[16];
    const float* cls_b2    = (const float*)d_in[17];
    const int*   pos       = (const int*)d_in[18];
    const int*   emask     = (const int*)d_in[19];
    float* out = (float*)d_out;

    float *x, *qkv, *buf1, *buf2, *hid;
    cudaGetSymbolAddress((void**)&x,    g_x);
    cudaGetSymbolAddress((void**)&qkv,  g_qkv);
    cudaGetSymbolAddress((void**)&buf1, g_buf1);
    cudaGetSymbolAddress((void**)&buf2, g_buf2);
    cudaGetSymbolAddress((void**)&hid,  g_hid);

    pool_kernel<<<NT, 128>>>(lhs, attn_w, attn_b, pos, emask, x);

    for (int l = 0; l < Lv; l++) {
        // QKV projection [1024,768] @ [2304,768]^T
        gemm_tf32_kernel<<<dim3(36, 16), 128>>>(
            x, in_proj_w + (size_t)l * 3 * Dv * Dv, in_proj_b + (size_t)l * 3 * Dv,
            qkv, 3 * Dv, Dv, 0);
        // self-attention
        attn_kernel<<<Bv * Hv, 256>>>(qkv, buf1);
        // output projection
        gemm_tf32_kernel<<<dim3(12, 16), 128>>>(
            buf1, out_w + (size_t)l * Dv * Dv, out_b + (size_t)l * Dv,
            buf2, Dv, Dv, 0);
        addln_kernel<<<NT, 256>>>(x, buf2, ln1_w + (size_t)l * Dv, ln1_b + (size_t)l * Dv);
        // FFN
        gemm_tf32_kernel<<<dim3(48, 16), 128>>>(
            x, lin1_w + (size_t)l * DFFv * Dv, lin1_b + (size_t)l * DFFv,
            buf1, DFFv, Dv, 1);
        gemm_tf32_kernel<<<dim3(12, 16), 128>>>(
            buf1, lin2_w + (size_t)l * Dv * DFFv, lin2_b + (size_t)l * Dv,
            buf2, Dv, DFFv, 0);
        addln_kernel<<<NT, 256>>>(x, buf2, ln2_w + (size_t)l * Dv, ln2_b + (size_t)l * Dv);
    }

    // classifier
    gemm_tf32_kernel<<<dim3(2, 16), 128>>>(x, cls_w1, nullptr, hid, 100, Dv, 0);
    gemm_tf32_kernel<<<dim3(1563, 16), 128>>>(hid, cls_w2, cls_b2, out, Ev, 100, 0);
}

// round 3
// speedup vs baseline: 3.4469x; 1.7289x over previous
#include <cuda_runtime.h>
#include <math.h>
#include <stdint.h>

// Problem constants
#define Bv   32
#define Sv   512
#define Dv   768
#define Mv   32
#define Tv   30
#define Hv   12
#define HDv  64
#define DFFv 3072
#define Lv   4
#define Ev   100000
#define NT   1024           // B*M token rows

// ---------------- scratch (static device memory; no allocations) -------------
__device__ float g_x[NT * Dv];          // residual stream
__device__ float g_qkv[NT * 3 * Dv];    // [1024,2304]
__device__ float g_buf1[NT * DFFv];     // attn-out / FF hidden
__device__ float g_hid[NT * 128];       // classifier hidden (padded)
__device__ float g_part[8 * NT * Dv];   // split-K partials (max 8*768 = 2*3072 cols)

// ======================= helpers ============================================
__device__ __forceinline__ uint32_t f2tf32(float f) {
    uint32_t u;
    asm("cvt.rna.tf32.f32 %0, %1;" : "=r"(u) : "f"(f));
    return u;
}

__device__ __forceinline__ void mma_tf32(float* c, const uint32_t* a, const uint32_t* b) {
    asm volatile(
        "mma.sync.aligned.m16n8k8.row.col.f32.tf32.tf32.f32 "
        "{%0,%1,%2,%3}, {%4,%5,%6,%7}, {%8,%9}, {%0,%1,%2,%3};"
        : "+f"(c[0]), "+f"(c[1]), "+f"(c[2]), "+f"(c[3])
        : "r"(a[0]), "r"(a[1]), "r"(a[2]), "r"(a[3]),
          "r"(b[0]), "r"(b[1]));
}

__device__ __forceinline__ void cp16(unsigned dst, const float* src, int bytes) {
    asm volatile("cp.async.ca.shared.global [%0], [%1], 16, %2;\n"
                 :: "r"(dst), "l"(src), "r"(bytes));
}

// ======================= mention pooling ====================================
__global__ void __launch_bounds__(128) pool_kernel(
    const float* __restrict__ lhs, const float* __restrict__ attn_w,
    const float* __restrict__ attn_b_p, const int* __restrict__ pos,
    const int* __restrict__ emask, float* __restrict__ x)
{
    int bm = blockIdx.x;
    int b = bm / Mv;
    __shared__ float logit[Tv];
    __shared__ float score[Tv];
    __shared__ int   validv[Tv];

    int tid = threadIdx.x, lane = tid & 31, warp = tid >> 5;

    if (tid == 0) {
        int ok = (emask[bm] != 0);
        int alive = 1;
        for (int t = 0; t < Tv; t++) {
            if (pos[bm * Tv + t] == -1) alive = 0;
            validv[t] = ok & alive;
        }
    }
    __syncthreads();

    float ab = attn_b_p[0];
    const float* lb = lhs + (size_t)b * Sv * Dv;

    for (int t = warp; t < Tv; t += 4) {
        float s = 0.f;
        for (int d = lane; d < Dv; d += 32) s += lb[t * Dv + d] * attn_w[d];
        for (int o = 16; o; o >>= 1) s += __shfl_xor_sync(0xffffffffu, s, o);
        if (lane == 0) logit[t] = (validv[t] ? s : 0.f) + ab;
    }
    __syncthreads();

    if (tid < 32) {
        float v = (tid < Tv) ? logit[tid] : -INFINITY;
        float mx = v;
        for (int o = 16; o; o >>= 1) mx = fmaxf(mx, __shfl_xor_sync(0xffffffffu, mx, o));
        float e = (tid < Tv) ? expf(v - mx) : 0.f;
        float sm = e;
        for (int o = 16; o; o >>= 1) sm += __shfl_xor_sync(0xffffffffu, sm, o);
        if (tid < Tv) score[tid] = e / sm;
    }
    __syncthreads();

    for (int d = tid; d < Dv; d += 128) {
        float s = 0.f;
        #pragma unroll
        for (int t = 0; t < Tv; t++)
            if (validv[t]) s += score[t] * lb[t * Dv + d];
        x[(size_t)bm * Dv + d] = s;
    }
}

// ======================= TF32 tensor-core GEMM v2 ===========================
// C = A @ W^T. A:[1024,K] fp32 row-major, W:[N,K] fp32 row-major.
// Tile 128x128x32, 256 threads, 8 warps (2x4), warp tile 64x32.
// Double-buffered cp.async (fp32 in smem, cvt.rna at consume).
// grid = (ceil(N/128), 8, kSplit). If kSplit>1 -> C is partial buffer
// (stride 1024*N per split), bias must be null, relu 0.
#define SMS 4608   // floats per tile stage: 128*36

__device__ __forceinline__ void fill_tiles(
    float* As, float* Ws, const float* __restrict__ A, const float* __restrict__ W,
    int rowBase, int colBase, int N, int K, int k0, int kEnd, int tid)
{
    #pragma unroll
    for (int i = 0; i < 4; i++) {
        int c = tid + i * 256;          // 0..1023
        int r = c >> 3, ck = c & 7;
        int gk = k0 + ck * 4;
        int ok = (gk < kEnd);
        const float* src = ok ? (A + (size_t)(rowBase + r) * K + gk) : A;
        unsigned d = (unsigned)__cvta_generic_to_shared(As + r * 36 + ck * 4);
        cp16(d, src, ok ? 16 : 0);
    }
    #pragma unroll
    for (int i = 0; i < 4; i++) {
        int c = tid + i * 256;
        int r = c >> 3, ck = c & 7;
        int gk = k0 + ck * 4;
        int n = colBase + r;
        int ok = (n < N) && (gk < kEnd);
        const float* src = ok ? (W + (size_t)n * K + gk) : W;
        unsigned d = (unsigned)__cvta_generic_to_shared(Ws + r * 36 + ck * 4);
        cp16(d, src, ok ? 16 : 0);
    }
}

__global__ void __launch_bounds__(256) gemm_tc(
    const float* __restrict__ A, const float* __restrict__ W,
    const float* __restrict__ bias, float* __restrict__ C,
    int N, int K, int kChunk, int relu)
{
    extern __shared__ float smbuf[];
    float* AsBase = smbuf;              // [2][128][36]
    float* WsBase = smbuf + 2 * SMS;    // [2][128][36]

    const int tid = threadIdx.x;
    const int lane = tid & 31, wid = tid >> 5;
    const int wy = wid >> 2, wx = wid & 3;      // 2 x 4 warps
    const int lm = lane >> 2, lk = lane & 3;
    const int rowBase = blockIdx.y * 128;
    const int colBase = blockIdx.x * 128;
    const int kBase = blockIdx.z * kChunk;
    const int kEnd = min(K, kBase + kChunk);
    const int nT = (kEnd - kBase + 31) >> 5;

    float* Cp = C;
    if (gridDim.z > 1) Cp += (size_t)blockIdx.z * ((size_t)NT * N);

    float acc[4][4][4];
    #pragma unroll
    for (int i = 0; i < 4; i++)
        #pragma unroll
        for (int j = 0; j < 4; j++)
            #pragma unroll
            for (int q = 0; q < 4; q++) acc[i][j][q] = 0.f;

    fill_tiles(AsBase, WsBase, A, W, rowBase, colBase, N, K, kBase, kEnd, tid);
    asm volatile("cp.async.commit_group;\n" ::: "memory");

    for (int t = 0; t < nT; t++) {
        const int cur = t & 1;
        if (t + 1 < nT)
            fill_tiles(AsBase + (cur ^ 1) * SMS, WsBase + (cur ^ 1) * SMS,
                       A, W, rowBase, colBase, N, K, kBase + (t + 1) * 32, kEnd, tid);
        asm volatile("cp.async.commit_group;\n" ::: "memory");
        asm volatile("cp.async.wait_group 1;\n" ::: "memory");
        __syncthreads();

        const float* as = AsBase + cur * SMS;
        const float* ws = WsBase + cur * SMS;
        #pragma unroll
        for (int k8 = 0; k8 < 4; k8++) {
            const int kb = k8 * 8;
            uint32_t af[4][4], bf[4][2];
            #pragma unroll
            for (int mt = 0; mt < 4; mt++) {
                int m = wy * 64 + mt * 16 + lm;
                af[mt][0] = f2tf32(as[m * 36 + kb + lk]);
                af[mt][1] = f2tf32(as[(m + 8) * 36 + kb + lk]);
                af[mt][2] = f2tf32(as[m * 36 + kb + 4 + lk]);
                af[mt][3] = f2tf32(as[(m + 8) * 36 + kb + 4 + lk]);
            }
            #pragma unroll
            for (int nt = 0; nt < 4; nt++) {
                int n = wx * 32 + nt * 8 + lm;
                bf[nt][0] = f2tf32(ws[n * 36 + kb + lk]);
                bf[nt][1] = f2tf32(ws[n * 36 + kb + 4 + lk]);
            }
            #pragma unroll
            for (int mt = 0; mt < 4; mt++)
                #pragma unroll
                for (int nt = 0; nt < 4; nt++)
                    mma_tf32(acc[mt][nt], af[mt], bf[nt]);
        }
        __syncthreads();
    }

    // epilogue
    #pragma unroll
    for (int mt = 0; mt < 4; mt++) {
        #pragma unroll
        for (int nt = 0; nt < 4; nt++) {
            int r0 = rowBase + wy * 64 + mt * 16 + lm;
            int c0 = colBase + wx * 32 + nt * 8 + lk * 2;
            float bx = 0.f, by = 0.f;
            if (bias) {
                if (c0 < N)     bx = bias[c0];
                if (c0 + 1 < N) by = bias[c0 + 1];
            }
            float v00 = acc[mt][nt][0] + bx, v01 = acc[mt][nt][1] + by;
            float v10 = acc[mt][nt][2] + bx, v11 = acc[mt][nt][3] + by;
            if (relu) {
                v00 = fmaxf(v00, 0.f); v01 = fmaxf(v01, 0.f);
                v10 = fmaxf(v10, 0.f); v11 = fmaxf(v11, 0.f);
            }
            if (c0 + 1 < N) {
                *(float2*)&Cp[(size_t)r0 * N + c0]       = make_float2(v00, v01);
                *(float2*)&Cp[(size_t)(r0 + 8) * N + c0] = make_float2(v10, v11);
            } else if (c0 < N) {
                Cp[(size_t)r0 * N + c0]       = v00;
                Cp[(size_t)(r0 + 8) * N + c0] = v10;
            }
        }
    }
}

// ======================= attention (seq 32, hd 64), one block per (b,h) =====
__global__ void __launch_bounds__(256) attn_kernel(
    const float* __restrict__ qkv, float* __restrict__ o)
{
    const int bh = blockIdx.x;
    const int b = bh / Hv, h = bh % Hv;
    __shared__ float q[32][68];
    __shared__ float kk[32][68];
    __shared__ float vv[32][68];
    __shared__ float a[32][33];

    const int tid = threadIdx.x;
    const float* base = qkv + (size_t)(b * Mv) * (3 * Dv) + h * HDv;

    for (int idx = tid; idx < 32 * 64; idx += 256) {
        int i = idx >> 6, d = idx & 63;
        const float* row = base + (size_t)i * (3 * Dv) + d;
        q[i][d]  = row[0];
        kk[i][d] = row[Dv];
        vv[i][d] = row[2 * Dv];
    }
    __syncthreads();

    for (int idx = tid; idx < 1024; idx += 256) {
        int i = idx >> 5, j = idx & 31;
        float s = 0.f;
        #pragma unroll
        for (int d = 0; d < 64; d += 4) {
            float4 qa = *(const float4*)&q[i][d];
            float4 ka = *(const float4*)&kk[j][d];
            s += qa.x * ka.x + qa.y * ka.y + qa.z * ka.z + qa.w * ka.w;
        }
        a[i][j] = s * 0.125f;
    }
    __syncthreads();

    int warp = tid >> 5, lane = tid & 31;
    for (int i = warp; i < 32; i += 8) {
        float v = a[i][lane];
        float mx = v;
        for (int off = 16; off; off >>= 1) mx = fmaxf(mx, __shfl_xor_sync(0xffffffffu, mx, off));
        float e = expf(v - mx);
        float sm = e;
        for (int off = 16; off; off >>= 1) sm += __shfl_xor_sync(0xffffffffu, sm, off);
        a[i][lane] = e / sm;
    }
    __syncthreads();

    float* obase = o + (size_t)(b * Mv) * Dv + h * HDv;
    for (int idx = tid; idx < 2048; idx += 256) {
        int i = idx >> 6, d = idx & 63;
        float s = 0.f;
        #pragma unroll
        for (int j = 0; j < 32; j++) s += a[i][j] * vv[j][d];
        obase[(size_t)i * Dv + d] = s;
    }
}

// ================ reduce split-K partials + bias (+relu), elementwise =======
__global__ void __launch_bounds__(256) reduce_bias_kernel(
    float* __restrict__ dst, const float* __restrict__ part, int nPart,
    const float* __restrict__ bias, int Ncols, int relu)
{
    const size_t total = (size_t)NT * Ncols;
    const size_t stride = (size_t)gridDim.x * blockDim.x;
    for (size_t idx = (size_t)blockIdx.x * blockDim.x + threadIdx.x;
         idx < total; idx += stride) {
        float s = 0.f;
        for (int p = 0; p < nPart; p++) s += part[(size_t)p * total + idx];
        if (bias) s += bias[idx % Ncols];
        if (relu) s = fmaxf(s, 0.f);
        dst[idx] = s;
    }
}

// ======== reduce split-K partials + bias + residual add + LayerNorm =========
__global__ void __launch_bounds__(256) reduce_addln_kernel(
    float* __restrict__ x, const float* __restrict__ part, int nPart,
    const float* __restrict__ bias,
    const float* __restrict__ w, const float* __restrict__ b)
{
    __shared__ float sh[8];
    __shared__ float s_mean, s_inv;
    const int row = blockIdx.x;
    float* xr = x + (size_t)row * Dv;
    const int tid = threadIdx.x, lane = tid & 31, warp = tid >> 5;
    const size_t planeStride = (size_t)NT * Dv;

    float v[3];
    float sum = 0.f;
    #pragma unroll
    for (int i = 0; i < 3; i++) {
        int idx = tid + 256 * i;
        float d = bias[idx];
        for (int p = 0; p < nPart; p++)
            d += part[(size_t)p * planeStride + (size_t)row * Dv + idx];
        v[i] = xr[idx] + d;
        sum += v[i];
    }
    for (int o = 16; o; o >>= 1) sum += __shfl_xor_sync(0xffffffffu, sum, o);
    if (lane == 0) sh[warp] = sum;
    __syncthreads();
    if (tid == 0) {
        float s = 0.f;
        for (int i = 0; i < 8; i++) s += sh[i];
        s_mean = s * (1.f / (float)Dv);
    }
    __syncthreads();
    float mean = s_mean;

    float sq = 0.f;
    #pragma unroll
    for (int i = 0; i < 3; i++) { float c = v[i] - mean; sq += c * c; }
    for (int o = 16; o; o >>= 1) sq += __shfl_xor_sync(0xffffffffu, sq, o);
    if (lane == 0) sh[warp] = sq;
    __syncthreads();
    if (tid == 0) {
        float s = 0.f;
        for (int i = 0; i < 8; i++) s += sh[i];
        s_inv = rsqrtf(s * (1.f / (float)Dv) + 1e-5f);
    }
    __syncthreads();
    float inv = s_inv;

    #pragma unroll
    for (int i = 0; i < 3; i++) {
        int idx = tid + 256 * i;
        xr[idx] = (v[i] - mean) * inv * w[idx] + b[idx];
    }
}

// ======================= launcher ===========================================
#define GEMM_SMEM (4 * SMS * (int)sizeof(float))   // 73728 bytes

extern "C" void kernel_launch(void* const* d_in, const int* in_sizes, int n_in,
                              void* d_out, int out_size)
{
    const float* lhs       = (const float*)d_in[0];
    const float* attn_w    = (const float*)d_in[1];
    const float* attn_b    = (const float*)d_in[2];
    const float* in_proj_w = (const float*)d_in[3];
    const float* in_proj_b = (const float*)d_in[4];
    const float* out_w     = (const float*)d_in[5];
    const float* out_b     = (const float*)d_in[6];
    const float* ln1_w     = (const float*)d_in[7];
    const float* ln1_b     = (const float*)d_in[8];
    const float* lin1_w    = (const float*)d_in[9];
    const float* lin1_b    = (const float*)d_in[10];
    const float* lin2_w    = (const float*)d_in[11];
    const float* lin2_b    = (const float*)d_in[12];
    const float* ln2_w     = (const float*)d_in[13];
    const float* ln2_b     = (const float*)d_in[14];
    const float* cls_w1    = (const float*)d_in[15];
    const float* cls_w2    = (const float*)d_in[16];
    const float* cls_b2    = (const float*)d_in[17];
    const int*   pos       = (const int*)d_in[18];
    const int*   emask     = (const int*)d_in[19];
    float* out = (float*)d_out;

    float *x, *qkv, *buf1, *hid, *part;
    cudaGetSymbolAddress((void**)&x,    g_x);
    cudaGetSymbolAddress((void**)&qkv,  g_qkv);
    cudaGetSymbolAddress((void**)&buf1, g_buf1);
    cudaGetSymbolAddress((void**)&hid,  g_hid);
    cudaGetSymbolAddress((void**)&part, g_part);

    cudaFuncSetAttribute(gemm_tc, cudaFuncAttributeMaxDynamicSharedMemorySize, GEMM_SMEM);

    pool_kernel<<<NT, 128>>>(lhs, attn_w, attn_b, pos, emask, x);

    for (int l = 0; l < Lv; l++) {
        // QKV: [1024,768] @ [2304,768]^T, split-K 2
        gemm_tc<<<dim3(18, 8, 2), 256, GEMM_SMEM>>>(
            x, in_proj_w + (size_t)l * 3 * Dv * Dv, nullptr, part, 3 * Dv, Dv, 384, 0);
        reduce_bias_kernel<<<1024, 256>>>(qkv, part, 2, in_proj_b + (size_t)l * 3 * Dv, 3 * Dv, 0);
        // self-attention
        attn_kernel<<<Bv * Hv, 256>>>(qkv, buf1);
        // out-proj: [1024,768] @ [768,768]^T, split-K 4
        gemm_tc<<<dim3(6, 8, 4), 256, GEMM_SMEM>>>(
            buf1, out_w + (size_t)l * Dv * Dv, nullptr, part, Dv, Dv, 192, 0);
        reduce_addln_kernel<<<NT, 256>>>(x, part, 4, out_b + (size_t)l * Dv,
                                         ln1_w + (size_t)l * Dv, ln1_b + (size_t)l * Dv);
        // lin1: [1024,768] @ [3072,768]^T, split-K 2, relu in reduce
        gemm_tc<<<dim3(24, 8, 2), 256, GEMM_SMEM>>>(
            x, lin1_w + (size_t)l * DFFv * Dv, nullptr, part, DFFv, Dv, 384, 0);
        reduce_bias_kernel<<<1024, 256>>>(buf1, part, 2, lin1_b + (size_t)l * DFFv, DFFv, 1);
        // lin2: [1024,3072] @ [768,3072]^T, split-K 8
        gemm_tc<<<dim3(6, 8, 8), 256, GEMM_SMEM>>>(
            buf1, lin2_w + (size_t)l * Dv * DFFv, nullptr, part, Dv, DFFv, 384, 0);
        reduce_addln_kernel<<<NT, 256>>>(x, part, 8, lin2_b + (size_t)l * Dv,
                                         ln2_w + (size_t)l * Dv, ln2_b + (size_t)l * Dv);
    }

    // classifier stage 1: [1024,768] @ [100,768]^T, split-K 4
    gemm_tc<<<dim3(1, 8, 4), 256, GEMM_SMEM>>>(
        x, cls_w1, nullptr, part, 100, Dv, 192, 0);
    reduce_bias_kernel<<<1024, 256>>>(hid, part, 4, nullptr, 100, 0);
    // classifier stage 2: [1024,100] @ [100000,100]^T, direct
    gemm_tc<<<dim3(782, 8, 1), 256, GEMM_SMEM>>>(
        hid, cls_w2, cls_b2, out, Ev, 100, 100, 0);
}